// round 2
// baseline (speedup 1.0000x reference)
#include <cuda_runtime.h>
#include <cstdint>

// ColorCurveLearningLoss: per-(channel,bin) masked means of pred/target keyed by
// input_img bins, then mean |pred_curve - target_curve| over 96 segments.
//
// Algebra: mean_p - mean_t = sum(p - t)/cnt per bin (same count), so we only
// accumulate one fixed-point sum of d = p - t plus a count per bin, packed into
// a single 64-bit token: token = (1<<46) + (round(d*2^30) + 2^30).
//   - count field: bits [46,64)  (per-warp-per-block counts << 2^18)
//   - value field: bits [0,46)   (max per-warp ~1.3k elems * 2^31 ~= 2^42 < 2^46)
// One shared 64-bit atomicAdd per element; per-warp private histograms to avoid
// cross-warp same-address serialization; exact integer global reduction.

#define NBINS 32
#define NSEG 96
#define NWARPS 8
#define BLOCK 256
#define GRID 1184  // 148 SMs * 8 blocks

__device__ unsigned long long g_q[NSEG];    // fixed-point sum(p-t)*2^30, two's complement
__device__ unsigned long long g_cnt[NSEG];

__global__ void ccl_zero_kernel() {
    int i = threadIdx.x;
    if (i < NSEG) { g_q[i] = 0ull; g_cnt[i] = 0ull; }
}

__global__ void __launch_bounds__(BLOCK, 8) ccl_hist_kernel(
    const float* __restrict__ pred,
    const float* __restrict__ target,
    const float* __restrict__ ximg,
    int ngroups,     // total elements / 4
    int ch_shift)    // log2(elements-per-channel-per-image-batch-span / 4) chunk period in groups
{
    __shared__ unsigned long long hist[NWARPS][NSEG];
    const int tid  = threadIdx.x;
    const int warp = tid >> 5;

    for (int i = tid; i < NWARPS * NSEG; i += BLOCK)
        (&hist[0][0])[i] = 0ull;
    __syncthreads();

    unsigned long long* h = hist[warp];
    const float4* __restrict__ x4 = (const float4*)ximg;
    const float4* __restrict__ p4 = (const float4*)pred;
    const float4* __restrict__ t4 = (const float4*)target;

    const int stride = GRID * BLOCK;
    for (int g = blockIdx.x * BLOCK + tid; g < ngroups; g += stride) {
        float4 xv = __ldg(x4 + g);
        float4 pv = __ldg(p4 + g);
        float4 tv = __ldg(t4 + g);
        int ch   = (g >> ch_shift) % 3;
        int base = ch * NBINS;

        float xs[4] = { xv.x, xv.y, xv.z, xv.w };
        float ds[4] = { pv.x - tv.x, pv.y - tv.y, pv.z - tv.z, pv.w - tv.w };

        #pragma unroll
        for (int j = 0; j < 4; j++) {
            // bin = floor(x*32): exact (power-of-two multiply, x in [0,1)).
            int b = (int)(xs[j] * 32.0f);
            if ((unsigned)b < 32u) {   // drop x >= 1.0 or x < 0 (matches reference)
                int q = __float2int_rn(ds[j] * 1073741824.0f);  // d * 2^30
                unsigned long long tok =
                    (1ull << 46) + (unsigned long long)(unsigned)(q + (1 << 30));
                atomicAdd(&h[base + b], tok);
            }
        }
    }
    __syncthreads();

    // Merge per-warp copies, unpack fields, push exact integers to global.
    for (int b = tid; b < NSEG; b += BLOCK) {
        long long sumq = 0;
        unsigned long long cnt = 0;
        #pragma unroll
        for (int w = 0; w < NWARPS; w++) {
            unsigned long long wd = hist[w][b];
            unsigned long long c  = wd >> 46;
            long long low = (long long)(wd & ((1ull << 46) - 1ull));
            sumq += low - ((long long)c << 30);   // remove per-element +2^30 offset
            cnt  += c;
        }
        if (cnt) {
            atomicAdd(&g_q[b],  (unsigned long long)sumq);
            atomicAdd(&g_cnt[b], cnt);
        }
    }
}

__global__ void ccl_final_kernel(float* __restrict__ out) {
    __shared__ double warp_sum[4];
    int i = threadIdx.x;  // 128 threads
    double v = 0.0;
    if (i < NSEG) {
        unsigned long long c = g_cnt[i];
        if (c) {
            long long q = (long long)g_q[i];
            v = fabs((double)q / ((double)c * 1073741824.0));
        }
    }
    // warp reduce
    #pragma unroll
    for (int off = 16; off > 0; off >>= 1)
        v += __shfl_down_sync(0xffffffffu, v, off);
    if ((i & 31) == 0) warp_sum[i >> 5] = v;
    __syncthreads();
    if (i == 0) {
        double total = warp_sum[0] + warp_sum[1] + warp_sum[2] + warp_sum[3];
        out[0] = (float)(total / 96.0);
    }
}

extern "C" void kernel_launch(void* const* d_in, const int* in_sizes, int n_in,
                              void* d_out, int out_size) {
    const float* pred   = (const float*)d_in[0];
    const float* target = (const float*)d_in[1];
    const float* ximg   = (const float*)d_in[2];
    int n = in_sizes[0];              // 16*3*512*512 = 12,582,912
    int ngroups = n >> 2;             // float4 groups (n divisible by 4)

    // channel = (element_idx / (H*W)) % 3; H*W = n / (16*3). In groups of 4:
    // period = (n/48) >> 2 = 65536 = 2^16 (power of two for this shape).
    int hw_groups = (n / 48) >> 2;
    int ch_shift = 0;
    while ((1 << ch_shift) < hw_groups) ch_shift++;

    ccl_zero_kernel<<<1, 96>>>();
    ccl_hist_kernel<<<GRID, BLOCK>>>(pred, target, ximg, ngroups, ch_shift);
    ccl_final_kernel<<<1, 128>>>((float*)d_out);
}

// round 4
// speedup vs baseline: 1.4477x; 1.4477x over previous
#include <cuda_runtime.h>
#include <cstdint>

// ColorCurveLearningLoss, single fused kernel.
// mean_p - mean_t = sum(p-t)/cnt per (channel,bin), so accumulate one packed
// 64-bit token per element: tok = (1<<46) + (round(d*2^30) + 2^30).
//   count field  bits [46,64), value field bits [0,46).
// Per-THREAD private smem histograms (no atomics), stored TRANSPOSED
// [bin][thread] so the bank index depends only on tid -> conflict-free RMW.
// Grid is partitioned by channel (layout: 48 contiguous 65536-group chunks,
// channel = chunk % 3), so each thread needs only 32 bins.
// Globals are self-cleaning: last block (grid-done counter) finalizes the
// loss, and resets all globals with atomicExch (coherent read + reset).

#define NBINS 32
#define NSEG 96
#define BLOCK 192           // 6 warps; hist = 32*192*8 = 49152 B (static smem limit)
#define NWARP (BLOCK / 32)
#define BLK_PER_CH 196
#define GRID (3 * BLK_PER_CH)
#define MASK46 ((1ull << 46) - 1ull)

__device__ unsigned long long g_q[NSEG];    // sum(p-t) * 2^30, two's complement
__device__ unsigned long long g_cnt[NSEG];
__device__ unsigned int g_done = 0;

__global__ void __launch_bounds__(BLOCK, 4) ccl_kernel(
    const float* __restrict__ pred,
    const float* __restrict__ target,
    const float* __restrict__ ximg,
    float* __restrict__ out,
    int hw_shift,    // log2(groups per channel-chunk) = 16 for this shape
    int nchunks)     // chunks per channel = 16
{
    __shared__ unsigned long long hist[NBINS][BLOCK];   // transposed: [bin][thread]
    const int tid  = threadIdx.x;
    const int ch   = blockIdx.x / BLK_PER_CH;           // 0..2
    const int blk  = blockIdx.x % BLK_PER_CH;
    const int lane = tid & 31;
    const int warp = tid >> 5;

    // Linear zero (conflict-free), then sync since columns cross threads.
    {
        unsigned long long* flat = &hist[0][0];
        #pragma unroll
        for (int i = 0; i < NBINS; i++) flat[i * BLOCK + tid] = 0ull;
    }
    __syncthreads();

    const float4* __restrict__ x4 = (const float4*)ximg;
    const float4* __restrict__ p4 = (const float4*)pred;
    const float4* __restrict__ t4 = (const float4*)target;

    unsigned long long* h = &hist[0][tid];   // h[b*BLOCK] == hist[b][tid]
    const int mask  = (1 << hw_shift) - 1;
    const int total = nchunks << hw_shift;   // groups per channel

    for (int i = blk * BLOCK + tid; i < total; i += BLK_PER_CH * BLOCK) {
        int chunk = i >> hw_shift;
        int g = ((chunk * 3 + ch) << hw_shift) + (i & mask);
        float4 xv = __ldg(x4 + g);
        float4 pv = __ldg(p4 + g);
        float4 tv = __ldg(t4 + g);

        float xs[4] = { xv.x, xv.y, xv.z, xv.w };
        float ds[4] = { pv.x - tv.x, pv.y - tv.y, pv.z - tv.z, pv.w - tv.w };

        #pragma unroll
        for (int j = 0; j < 4; j++) {
            int b = (int)(xs[j] * 32.0f);           // exact floor(x*32), x in [0,1)
            if ((unsigned)b < 32u) {
                int q = __float2int_rn(ds[j] * 1073741824.0f);   // d * 2^30
                unsigned long long tok =
                    (1ull << 46) + (unsigned long long)(unsigned)(q + (1 << 30));
                h[b * BLOCK] += tok;                // plain smem RMW, own column
            }
        }
    }
    __syncthreads();

    // Epilogue: warp w sweeps bins w, w+6, ... — lane l reads column l+32j
    // (coalesced, conflict-free), shuffle-reduce, 2 global atomics per bin.
    for (int b = warp; b < NBINS; b += NWARP) {
        long long sumq = 0;
        long long cnt  = 0;
        #pragma unroll
        for (int j = 0; j < NWARP; j++) {
            unsigned long long wd = hist[b][lane + 32 * j];
            unsigned long long cc = wd >> 46;
            sumq += (long long)(wd & MASK46) - ((long long)cc << 30);
            cnt  += (long long)cc;
        }
        #pragma unroll
        for (int off = 16; off; off >>= 1) {
            sumq += __shfl_down_sync(0xffffffffu, sumq, off);
            cnt  += __shfl_down_sync(0xffffffffu, cnt,  off);
        }
        if (lane == 0 && cnt) {
            atomicAdd(&g_q[ch * NBINS + b], (unsigned long long)sumq);
            atomicAdd(&g_cnt[ch * NBINS + b], (unsigned long long)cnt);
        }
    }

    // Grid-done handshake; hist is dead past this sync -> reuse as scratch.
    __threadfence();
    __syncthreads();
    unsigned* lastflag = (unsigned*)&hist[0][0];
    double*   ws       = (double*)&hist[1][0];
    if (tid == 0) {
        unsigned old = atomicAdd(&g_done, 1u);
        lastflag[0] = (old == GRID - 1) ? 1u : 0u;
    }
    __syncthreads();
    if (lastflag[0]) {
        double v = 0.0;
        if (tid < NSEG) {
            unsigned long long cc = atomicExch(&g_cnt[tid], 0ull);  // coherent read + reset
            long long qq = (long long)atomicExch(&g_q[tid], 0ull);
            if (cc) v = fabs((double)qq / ((double)cc * 1073741824.0));
        }
        #pragma unroll
        for (int off = 16; off; off >>= 1)
            v += __shfl_down_sync(0xffffffffu, v, off);
        if (lane == 0) ws[warp] = v;
        __syncthreads();
        if (tid == 0) {
            double tot = 0.0;
            #pragma unroll
            for (int w = 0; w < NWARP; w++) tot += ws[w];
            out[0] = (float)(tot / 96.0);
            atomicExch(&g_done, 0u);   // self-clean for next replay
        }
    }
}

extern "C" void kernel_launch(void* const* d_in, const int* in_sizes, int n_in,
                              void* d_out, int out_size) {
    const float* pred   = (const float*)d_in[0];
    const float* target = (const float*)d_in[1];
    const float* ximg   = (const float*)d_in[2];
    int n = in_sizes[0];              // 16*3*512*512 = 12,582,912

    // groups per channel-chunk (H*W/4 = 65536 = 2^16 for this shape)
    int hwg = (n / 48) >> 2;
    int hw_shift = 0;
    while ((1 << hw_shift) < hwg) hw_shift++;
    int nchunks = (n >> 2) / (3 * hwg);   // 16

    ccl_kernel<<<GRID, BLOCK>>>(pred, target, ximg, (float*)d_out,
                                hw_shift, nchunks);
}